// round 6
// baseline (speedup 1.0000x reference)
#include <cuda_runtime.h>
#include <cuda_fp16.h>

#define D 128
#define MAX_N 100000
#define MBLK 64            // rows of x per GEMM block
#define PADH 136           // smem row stride in halves
#define EPB 512            // edges per scatter block
#define CPB 4              // chains per block
#define CLEN (EPB / CPB)   // 128 edges per chain

// support = x@W + b, stored fp16 (25.6 MB)
__device__ __half g_support_h[(size_t)MAX_N * D];
// W transposed + converted to fp16: Wt[n][k]
__device__ __half g_Wt_h[D * D];

// ---------------------------------------------------------------------------
// prep: Wt_h[n][k] = fp16(W[k][n])
// ---------------------------------------------------------------------------
__global__ void prep_kernel(const float* __restrict__ W, __half* __restrict__ Wt) {
    int i = blockIdx.x * blockDim.x + threadIdx.x;
    if (i < D * D) {
        int k = i >> 7, n = i & 127;
        Wt[n * D + k] = __float2half(W[i]);
    }
}

__device__ __forceinline__ void mma_f16(float d[4], unsigned a0, unsigned a1,
                                        unsigned a2, unsigned a3,
                                        unsigned b0, unsigned b1) {
    asm volatile(
        "mma.sync.aligned.m16n8k16.row.col.f32.f16.f16.f32 "
        "{%0,%1,%2,%3}, {%4,%5,%6,%7}, {%8,%9}, {%0,%1,%2,%3};"
        : "+f"(d[0]), "+f"(d[1]), "+f"(d[2]), "+f"(d[3])
        : "r"(a0), "r"(a1), "r"(a2), "r"(a3), "r"(b0), "r"(b1));
}

// ---------------------------------------------------------------------------
// GEMM: support = fp16(x@W + b) via fp16 mma m16n8k16. Also zeroes its rows
// of `out`. (Memory-floor bound; unchanged.)
// ---------------------------------------------------------------------------
__global__ void __launch_bounds__(256) gemm_mma_kernel(
        const float* __restrict__ x,
        const __half* __restrict__ Wt,
        const float* __restrict__ b,
        __half* __restrict__ sup,
        float* __restrict__ out, int N) {
    extern __shared__ __half smem[];
    __half* sX = smem;                 // 64  x PADH halves
    __half* sW = smem + MBLK * PADH;   // 128 x PADH halves ([n][k])

    const int tid  = threadIdx.x;
    const int lane = tid & 31;
    const int w    = tid >> 5;
    const int wm   = w & 3;
    const int wn   = w >> 2;
    const int g    = lane >> 2;
    const int tig  = lane & 3;

    const int row0 = blockIdx.x * MBLK;

    const uint4* Wv = (const uint4*)Wt;
    #pragma unroll
    for (int i = tid; i < 128 * 16; i += 256) {
        int r = i >> 4, c = i & 15;
        *(uint4*)(sW + r * PADH + c * 8) = Wv[i];
    }
    const float4* xv = (const float4*)x;
    #pragma unroll
    for (int i = tid; i < MBLK * 32; i += 256) {
        int r = i >> 5, c = i & 31;
        float4 v = make_float4(0.f, 0.f, 0.f, 0.f);
        if (row0 + r < N) v = xv[(size_t)(row0 + r) * 32 + c];
        __half2 h0 = __floats2half2_rn(v.x, v.y);
        __half2 h1 = __floats2half2_rn(v.z, v.w);
        uint2 p = make_uint2(*(unsigned*)&h0, *(unsigned*)&h1);
        *(uint2*)(sX + r * PADH + c * 4) = p;
    }
    __syncthreads();

    float acc[8][4];
    #pragma unroll
    for (int t = 0; t < 8; t++)
        #pragma unroll
        for (int j = 0; j < 4; j++) acc[t][j] = 0.f;

    const int ar0 = wm * 16 + g;
    const int ar1 = ar0 + 8;

    #pragma unroll
    for (int k0 = 0; k0 < D; k0 += 16) {
        unsigned a0 = *(const unsigned*)(sX + ar0 * PADH + k0 + 2 * tig);
        unsigned a1 = *(const unsigned*)(sX + ar1 * PADH + k0 + 2 * tig);
        unsigned a2 = *(const unsigned*)(sX + ar0 * PADH + k0 + 2 * tig + 8);
        unsigned a3 = *(const unsigned*)(sX + ar1 * PADH + k0 + 2 * tig + 8);
        #pragma unroll
        for (int t = 0; t < 8; t++) {
            int n0 = wn * 64 + t * 8;
            unsigned b0 = *(const unsigned*)(sW + (n0 + g) * PADH + k0 + 2 * tig);
            unsigned b1 = *(const unsigned*)(sW + (n0 + g) * PADH + k0 + 2 * tig + 8);
            mma_f16(acc[t], a0, a1, a2, a3, b0, b1);
        }
    }

    const int gr0 = row0 + wm * 16 + g;
    const int gr1 = gr0 + 8;
    #pragma unroll
    for (int t = 0; t < 8; t++) {
        int col = wn * 64 + t * 8 + 2 * tig;
        float bx = b[col], by = b[col + 1];
        if (gr0 < N) {
            __half2 h = __floats2half2_rn(acc[t][0] + bx, acc[t][1] + by);
            *(__half2*)(sup + (size_t)gr0 * D + col) = h;
        }
        if (gr1 < N) {
            __half2 h = __floats2half2_rn(acc[t][2] + bx, acc[t][3] + by);
            *(__half2*)(sup + (size_t)gr1 * D + col) = h;
        }
    }

    const float4 z4 = make_float4(0.f, 0.f, 0.f, 0.f);
    float4* outv = (float4*)out;
    #pragma unroll
    for (int i = tid; i < MBLK * 32; i += 256) {
        int r = i >> 5;
        if (row0 + r < N) outv[(size_t)(row0 + r) * 32 + (i & 31)] = z4;
    }
}

// ---------------------------------------------------------------------------
// Scatter: out[dst] += w_e * support[src]  (fp16 gather, fp32 accumulate).
// int4 metadata (1 LDS.128/edge), prefetch depth 2 (MLP=2 on the gather),
// run-accumulate; interior runs (sole chip-wide writer: edge_dst globally
// sorted) flush with STG.128; chain-boundary dsts use atomics.
// ---------------------------------------------------------------------------
__global__ void __launch_bounds__(128) scatter_kernel(
        const __half* __restrict__ sup,
        const float* __restrict__ ew,
        const int* __restrict__ esrc,
        const int* __restrict__ edst,
        float* __restrict__ out, int E) {
    __shared__ int4 s_m[EPB + 2];      // (src, dst, w_bits, pad), +2 sentinels

    const int base = blockIdx.x * EPB;
    const int n = min(EPB, E - base);

    for (int i = threadIdx.x; i < n; i += 128) {
        s_m[i] = make_int4(esrc[base + i], edst[base + i],
                           __float_as_int(ew[base + i]), 0);
    }
    __syncthreads();
    // Sentinels: same (valid) src/dst as last real edge, weight 0.
    for (int i = n + (int)threadIdx.x; i < EPB + 2; i += 128) {
        int4 t = s_m[n - 1];
        t.z = 0;                       // w = 0.0f
        s_m[i] = t;
    }
    __syncthreads();

    const int chain = threadIdx.x >> 5;
    const int lane  = threadIdx.x & 31;
    const int cbeg  = chain * CLEN;

    // Chain-boundary destinations (may have writers elsewhere)
    const int first_dst = s_m[cbeg].y;
    const int last_dst  = s_m[cbeg + CLEN - 1].y;

    const uint2* supv = (const uint2*)sup;

    int4  m0 = s_m[cbeg];
    int4  m1 = s_m[cbeg + 1];
    uint2 u0 = supv[(size_t)m0.x * 32 + lane];
    uint2 u1 = supv[(size_t)m1.x * 32 + lane];

    float4 acc = make_float4(0.f, 0.f, 0.f, 0.f);

    #pragma unroll 8
    for (int j = 0; j < CLEN; j++) {
        const int e = cbeg + j;
        // prefetch edge e+2 (sentinel/neighbor-chain reads are safe)
        int4  m2 = s_m[e + 2];
        uint2 u2 = supv[(size_t)m2.x * 32 + lane];

        const float w = __int_as_float(m0.z);
        float2 f0 = __half22float2(*(__half2*)(&u0.x));
        float2 f1 = __half22float2(*(__half2*)(&u0.y));
        acc.x += w * f0.x; acc.y += w * f0.y;
        acc.z += w * f1.x; acc.w += w * f1.y;

        if ((j == CLEN - 1) | (m0.y != m1.y)) {
            float* o = out + (size_t)m0.y * D + lane * 4;
            if ((m0.y != first_dst) & (m0.y != last_dst)) {
                *(float4*)o = acc;            // sole writer: plain store
            } else {
                atomicAdd(o + 0, acc.x);
                atomicAdd(o + 1, acc.y);
                atomicAdd(o + 2, acc.z);
                atomicAdd(o + 3, acc.w);
            }
            acc = make_float4(0.f, 0.f, 0.f, 0.f);
        }
        m0 = m1; m1 = m2;
        u0 = u1; u1 = u2;
    }
}

extern "C" void kernel_launch(void* const* d_in, const int* in_sizes, int n_in,
                              void* d_out, int out_size) {
    const float* x    = (const float*)d_in[0];
    const float* W    = (const float*)d_in[1];
    const float* b    = (const float*)d_in[2];
    const float* ew   = (const float*)d_in[3];
    const int*   esrc = (const int*)d_in[4];
    const int*   edst = (const int*)d_in[5];
    float* out = (float*)d_out;

    const int N = in_sizes[0] / D;
    const int E = in_sizes[3];

    __half* sup = nullptr;
    cudaGetSymbolAddress((void**)&sup, g_support_h);
    __half* Wt = nullptr;
    cudaGetSymbolAddress((void**)&Wt, g_Wt_h);

    prep_kernel<<<(D * D + 255) / 256, 256>>>(W, Wt);

    const int gemm_smem = (MBLK * PADH + D * PADH) * (int)sizeof(__half); // ~52 KB
    cudaFuncSetAttribute(gemm_mma_kernel, cudaFuncAttributeMaxDynamicSharedMemorySize, gemm_smem);

    const int gemm_blocks = (N + MBLK - 1) / MBLK;
    gemm_mma_kernel<<<gemm_blocks, 256, gemm_smem>>>(x, Wt, b, sup, out, N);

    const int scat_blocks = (E + EPB - 1) / EPB;
    scatter_kernel<<<scat_blocks, 128>>>(sup, ew, esrc, edst, out, E);
}

// round 7
// speedup vs baseline: 1.0464x; 1.0464x over previous
#include <cuda_runtime.h>
#include <cuda_fp16.h>

#define D 128
#define MAX_N 100000
#define MBLK 64            // rows of x per GEMM block
#define PADH 136           // smem row stride in halves

// support = x@W + b, stored fp16 (25.6 MB)
__device__ __half g_support_h[(size_t)MAX_N * D];
// W transposed + converted to fp16: Wt[n][k]
__device__ __half g_Wt_h[D * D];
// CSR row pointers for destination nodes
__device__ int g_rowptr[MAX_N + 1];

// ---------------------------------------------------------------------------
// prep: Wt_h[n][k] = fp16(W[k][n])
// ---------------------------------------------------------------------------
__global__ void prep_kernel(const float* __restrict__ W, __half* __restrict__ Wt) {
    int i = blockIdx.x * blockDim.x + threadIdx.x;
    if (i < D * D) {
        int k = i >> 7, n = i & 127;
        Wt[n * D + k] = __float2half(W[i]);
    }
}

// ---------------------------------------------------------------------------
// rowptr: edst is sorted -> rp[d] = index of first edge with dst >= d.
// Each thread fills the gap between edst[e-1] and edst[e]. Total work O(E+N).
// ---------------------------------------------------------------------------
__global__ void rowptr_kernel(const int* __restrict__ edst,
                              int* __restrict__ rp, int E, int N) {
    int e = blockIdx.x * blockDim.x + threadIdx.x;
    if (e >= E) return;
    int d  = edst[e];
    int dp = (e == 0) ? -1 : edst[e - 1];
    for (int k = dp + 1; k <= d; k++) rp[k] = e;
    if (e == E - 1)
        for (int k = d + 1; k <= N; k++) rp[k] = E;
}

__device__ __forceinline__ void mma_f16(float d[4], unsigned a0, unsigned a1,
                                        unsigned a2, unsigned a3,
                                        unsigned b0, unsigned b1) {
    asm volatile(
        "mma.sync.aligned.m16n8k16.row.col.f32.f16.f16.f32 "
        "{%0,%1,%2,%3}, {%4,%5,%6,%7}, {%8,%9}, {%0,%1,%2,%3};"
        : "+f"(d[0]), "+f"(d[1]), "+f"(d[2]), "+f"(d[3])
        : "r"(a0), "r"(a1), "r"(a2), "r"(a3), "r"(b0), "r"(b1));
}

// ---------------------------------------------------------------------------
// GEMM: support = fp16(x@W + b) via fp16 mma m16n8k16. (out zeroing removed:
// the CSR scatter writes every row exactly once.)
// ---------------------------------------------------------------------------
__global__ void __launch_bounds__(256) gemm_mma_kernel(
        const float* __restrict__ x,
        const __half* __restrict__ Wt,
        const float* __restrict__ b,
        __half* __restrict__ sup, int N) {
    extern __shared__ __half smem[];
    __half* sX = smem;                 // 64  x PADH halves
    __half* sW = smem + MBLK * PADH;   // 128 x PADH halves ([n][k])

    const int tid  = threadIdx.x;
    const int lane = tid & 31;
    const int w    = tid >> 5;
    const int wm   = w & 3;
    const int wn   = w >> 2;
    const int g    = lane >> 2;
    const int tig  = lane & 3;

    const int row0 = blockIdx.x * MBLK;

    const uint4* Wv = (const uint4*)Wt;
    #pragma unroll
    for (int i = tid; i < 128 * 16; i += 256) {
        int r = i >> 4, c = i & 15;
        *(uint4*)(sW + r * PADH + c * 8) = Wv[i];
    }
    const float4* xv = (const float4*)x;
    #pragma unroll
    for (int i = tid; i < MBLK * 32; i += 256) {
        int r = i >> 5, c = i & 31;
        float4 v = make_float4(0.f, 0.f, 0.f, 0.f);
        if (row0 + r < N) v = xv[(size_t)(row0 + r) * 32 + c];
        __half2 h0 = __floats2half2_rn(v.x, v.y);
        __half2 h1 = __floats2half2_rn(v.z, v.w);
        uint2 p = make_uint2(*(unsigned*)&h0, *(unsigned*)&h1);
        *(uint2*)(sX + r * PADH + c * 4) = p;
    }
    __syncthreads();

    float acc[8][4];
    #pragma unroll
    for (int t = 0; t < 8; t++)
        #pragma unroll
        for (int j = 0; j < 4; j++) acc[t][j] = 0.f;

    const int ar0 = wm * 16 + g;
    const int ar1 = ar0 + 8;

    #pragma unroll
    for (int k0 = 0; k0 < D; k0 += 16) {
        unsigned a0 = *(const unsigned*)(sX + ar0 * PADH + k0 + 2 * tig);
        unsigned a1 = *(const unsigned*)(sX + ar1 * PADH + k0 + 2 * tig);
        unsigned a2 = *(const unsigned*)(sX + ar0 * PADH + k0 + 2 * tig + 8);
        unsigned a3 = *(const unsigned*)(sX + ar1 * PADH + k0 + 2 * tig + 8);
        #pragma unroll
        for (int t = 0; t < 8; t++) {
            int n0 = wn * 64 + t * 8;
            unsigned b0 = *(const unsigned*)(sW + (n0 + g) * PADH + k0 + 2 * tig);
            unsigned b1 = *(const unsigned*)(sW + (n0 + g) * PADH + k0 + 2 * tig + 8);
            mma_f16(acc[t], a0, a1, a2, a3, b0, b1);
        }
    }

    const int gr0 = row0 + wm * 16 + g;
    const int gr1 = gr0 + 8;
    #pragma unroll
    for (int t = 0; t < 8; t++) {
        int col = wn * 64 + t * 8 + 2 * tig;
        float bx = b[col], by = b[col + 1];
        if (gr0 < N) {
            __half2 h = __floats2half2_rn(acc[t][0] + bx, acc[t][1] + by);
            *(__half2*)(sup + (size_t)gr0 * D + col) = h;
        }
        if (gr1 < N) {
            __half2 h = __floats2half2_rn(acc[t][2] + bx, acc[t][3] + by);
            *(__half2*)(sup + (size_t)gr1 * D + col) = h;
        }
    }
}

// ---------------------------------------------------------------------------
// CSR pull-scatter: one warp per destination node.
//   out[d][:] = sum_{e in [rp[d], rp[d+1])} w_e * support[src_e][:]
// Lane owns 4 features. Metadata loaded coalesced in 32-edge chunks, then
// broadcast via shfl. No atomics; single STG.128 per lane per node.
// ---------------------------------------------------------------------------
__global__ void __launch_bounds__(256) scatter_csr_kernel(
        const __half* __restrict__ sup,
        const float* __restrict__ ew,
        const int* __restrict__ esrc,
        const int* __restrict__ rp,
        float* __restrict__ out, int N) {
    const int warp = (blockIdx.x * blockDim.x + threadIdx.x) >> 5;
    const int lane = threadIdx.x & 31;
    if (warp >= N) return;

    const int beg = rp[warp];
    const int end = rp[warp + 1];

    const uint2* supv = (const uint2*)sup;
    float4 acc = make_float4(0.f, 0.f, 0.f, 0.f);

    for (int pos = beg; pos < end; pos += 32) {
        const int idx = pos + lane;
        int   s = 0;
        float w = 0.f;
        if (idx < end) { s = esrc[idx]; w = ew[idx]; }
        const int len = min(32, end - pos);

        #pragma unroll 4
        for (int j = 0; j < len; j++) {
            const int   sj = __shfl_sync(0xffffffffu, s, j);
            const float wj = __shfl_sync(0xffffffffu, w, j);
            uint2 u = supv[(size_t)sj * 32 + lane];
            float2 f0 = __half22float2(*(__half2*)(&u.x));
            float2 f1 = __half22float2(*(__half2*)(&u.y));
            acc.x += wj * f0.x; acc.y += wj * f0.y;
            acc.z += wj * f1.x; acc.w += wj * f1.y;
        }
    }

    *(float4*)(out + (size_t)warp * D + lane * 4) = acc;
}

extern "C" void kernel_launch(void* const* d_in, const int* in_sizes, int n_in,
                              void* d_out, int out_size) {
    const float* x    = (const float*)d_in[0];
    const float* W    = (const float*)d_in[1];
    const float* b    = (const float*)d_in[2];
    const float* ew   = (const float*)d_in[3];
    const int*   esrc = (const int*)d_in[4];
    const int*   edst = (const int*)d_in[5];
    float* out = (float*)d_out;

    const int N = in_sizes[0] / D;
    const int E = in_sizes[3];

    __half* sup = nullptr;
    cudaGetSymbolAddress((void**)&sup, g_support_h);
    __half* Wt = nullptr;
    cudaGetSymbolAddress((void**)&Wt, g_Wt_h);
    int* rp = nullptr;
    cudaGetSymbolAddress((void**)&rp, g_rowptr);

    prep_kernel<<<(D * D + 255) / 256, 256>>>(W, Wt);
    rowptr_kernel<<<(E + 255) / 256, 256>>>(edst, rp, E, N);

    const int gemm_smem = (MBLK * PADH + D * PADH) * (int)sizeof(__half); // ~52 KB
    cudaFuncSetAttribute(gemm_mma_kernel, cudaFuncAttributeMaxDynamicSharedMemorySize, gemm_smem);

    const int gemm_blocks = (N + MBLK - 1) / MBLK;
    gemm_mma_kernel<<<gemm_blocks, 256, gemm_smem>>>(x, Wt, b, sup, N);

    // one warp per node, 8 warps per block
    const int scat_blocks = (N + 7) / 8;
    scatter_csr_kernel<<<scat_blocks, 256>>>(sup, ew, esrc, rp, out, N);
}

// round 10
// speedup vs baseline: 1.1366x; 1.0862x over previous
#include <cuda_runtime.h>
#include <cuda_fp16.h>

#define D 128
#define MAX_N 100000
#define MBLK 64            // rows of x per GEMM block
#define PADH 136           // smem row stride in halves

// support = x@W + b, stored fp16 (25.6 MB)
__device__ __half g_support_h[(size_t)MAX_N * D];
// W transposed + converted to fp16: Wt[n][k]
__device__ __half g_Wt_h[D * D];
// CSR row pointers for destination nodes
__device__ int g_rowptr[MAX_N + 1];

// ---------------------------------------------------------------------------
// prep: Wt_h[n][k] = fp16(W[k][n])
// ---------------------------------------------------------------------------
__global__ void prep_kernel(const float* __restrict__ W, __half* __restrict__ Wt) {
    int i = blockIdx.x * blockDim.x + threadIdx.x;
    if (i < D * D) {
        int k = i >> 7, n = i & 127;
        Wt[n * D + k] = __float2half(W[i]);
    }
}

// ---------------------------------------------------------------------------
// rowptr: edst sorted -> rp[d] = first edge with dst >= d. O(E+N).
// ---------------------------------------------------------------------------
__global__ void rowptr_kernel(const int* __restrict__ edst,
                              int* __restrict__ rp, int E, int N) {
    int e = blockIdx.x * blockDim.x + threadIdx.x;
    if (e >= E) return;
    int d  = edst[e];
    int dp = (e == 0) ? -1 : edst[e - 1];
    for (int k = dp + 1; k <= d; k++) rp[k] = e;
    if (e == E - 1)
        for (int k = d + 1; k <= N; k++) rp[k] = E;
}

__device__ __forceinline__ void mma_f16(float d[4], unsigned a0, unsigned a1,
                                        unsigned a2, unsigned a3,
                                        unsigned b0, unsigned b1) {
    asm volatile(
        "mma.sync.aligned.m16n8k16.row.col.f32.f16.f16.f32 "
        "{%0,%1,%2,%3}, {%4,%5,%6,%7}, {%8,%9}, {%0,%1,%2,%3};"
        : "+f"(d[0]), "+f"(d[1]), "+f"(d[2]), "+f"(d[3])
        : "r"(a0), "r"(a1), "r"(a2), "r"(a3), "r"(b0), "r"(b1));
}

// ---------------------------------------------------------------------------
// GEMM: support = fp16(x@W + b) via fp16 mma m16n8k16. (Memory-floor bound.)
// ---------------------------------------------------------------------------
__global__ void __launch_bounds__(256) gemm_mma_kernel(
        const float* __restrict__ x,
        const __half* __restrict__ Wt,
        const float* __restrict__ b,
        __half* __restrict__ sup, int N) {
    extern __shared__ __half smem[];
    __half* sX = smem;                 // 64  x PADH halves
    __half* sW = smem + MBLK * PADH;   // 128 x PADH halves ([n][k])

    const int tid  = threadIdx.x;
    const int lane = tid & 31;
    const int w    = tid >> 5;
    const int wm   = w & 3;
    const int wn   = w >> 2;
    const int g    = lane >> 2;
    const int tig  = lane & 3;

    const int row0 = blockIdx.x * MBLK;

    const uint4* Wv = (const uint4*)Wt;
    #pragma unroll
    for (int i = tid; i < 128 * 16; i += 256) {
        int r = i >> 4, c = i & 15;
        *(uint4*)(sW + r * PADH + c * 8) = Wv[i];
    }
    const float4* xv = (const float4*)x;
    #pragma unroll
    for (int i = tid; i < MBLK * 32; i += 256) {
        int r = i >> 5, c = i & 31;
        float4 v = make_float4(0.f, 0.f, 0.f, 0.f);
        if (row0 + r < N) v = xv[(size_t)(row0 + r) * 32 + c];
        __half2 h0 = __floats2half2_rn(v.x, v.y);
        __half2 h1 = __floats2half2_rn(v.z, v.w);
        uint2 p = make_uint2(*(unsigned*)&h0, *(unsigned*)&h1);
        *(uint2*)(sX + r * PADH + c * 4) = p;
    }
    __syncthreads();

    float acc[8][4];
    #pragma unroll
    for (int t = 0; t < 8; t++)
        #pragma unroll
        for (int j = 0; j < 4; j++) acc[t][j] = 0.f;

    const int ar0 = wm * 16 + g;
    const int ar1 = ar0 + 8;

    #pragma unroll
    for (int k0 = 0; k0 < D; k0 += 16) {
        unsigned a0 = *(const unsigned*)(sX + ar0 * PADH + k0 + 2 * tig);
        unsigned a1 = *(const unsigned*)(sX + ar1 * PADH + k0 + 2 * tig);
        unsigned a2 = *(const unsigned*)(sX + ar0 * PADH + k0 + 2 * tig + 8);
        unsigned a3 = *(const unsigned*)(sX + ar1 * PADH + k0 + 2 * tig + 8);
        #pragma unroll
        for (int t = 0; t < 8; t++) {
            int n0 = wn * 64 + t * 8;
            unsigned b0 = *(const unsigned*)(sW + (n0 + g) * PADH + k0 + 2 * tig);
            unsigned b1 = *(const unsigned*)(sW + (n0 + g) * PADH + k0 + 2 * tig + 8);
            mma_f16(acc[t], a0, a1, a2, a3, b0, b1);
        }
    }

    const int gr0 = row0 + wm * 16 + g;
    const int gr1 = gr0 + 8;
    #pragma unroll
    for (int t = 0; t < 8; t++) {
        int col = wn * 64 + t * 8 + 2 * tig;
        float bx = b[col], by = b[col + 1];
        if (gr0 < N) {
            __half2 h = __floats2half2_rn(acc[t][0] + bx, acc[t][1] + by);
            *(__half2*)(sup + (size_t)gr0 * D + col) = h;
        }
        if (gr1 < N) {
            __half2 h = __floats2half2_rn(acc[t][2] + bx, acc[t][3] + by);
            *(__half2*)(sup + (size_t)gr1 * D + col) = h;
        }
    }
}

// ---------------------------------------------------------------------------
// CSR pull: one warp per destination node.
//   out[d][:] = sum_{e in [rp[d], rp[d+1])} w_e * support[src_e][:]
// Lane owns 4 features (uint2 gather — layout identical to the proven R7
// kernel). Metadata via warp-uniform LDG (L1 broadcast, one 128B line holds
// 32 edges). No shfl, no pipeline, no atomics; one STG.128 per lane per node.
// ---------------------------------------------------------------------------
__global__ void __launch_bounds__(256) scatter_csr_kernel(
        const __half* __restrict__ sup,
        const float* __restrict__ ew,
        const int* __restrict__ esrc,
        const int* __restrict__ rp,
        float* __restrict__ out, int N) {
    const int warp = (blockIdx.x * blockDim.x + threadIdx.x) >> 5;
    const int lane = threadIdx.x & 31;
    if (warp >= N) return;

    const int beg = rp[warp];
    const int end = rp[warp + 1];

    const uint2* supv = (const uint2*)sup;
    float4 acc = make_float4(0.f, 0.f, 0.f, 0.f);

    #pragma unroll 4
    for (int e = beg; e < end; e++) {
        const int   s = __ldg(esrc + e);   // warp-uniform -> L1 broadcast
        const float w = __ldg(ew + e);     // warp-uniform -> L1 broadcast
        uint2 u = supv[(size_t)s * 32 + lane];
        float2 f0 = __half22float2(*(__half2*)(&u.x));
        float2 f1 = __half22float2(*(__half2*)(&u.y));
        acc.x += w * f0.x; acc.y += w * f0.y;
        acc.z += w * f1.x; acc.w += w * f1.y;
    }

    *(float4*)(out + (size_t)warp * D + lane * 4) = acc;
}

extern "C" void kernel_launch(void* const* d_in, const int* in_sizes, int n_in,
                              void* d_out, int out_size) {
    const float* x    = (const float*)d_in[0];
    const float* W    = (const float*)d_in[1];
    const float* b    = (const float*)d_in[2];
    const float* ew   = (const float*)d_in[3];
    const int*   esrc = (const int*)d_in[4];
    const int*   edst = (const int*)d_in[5];
    float* out = (float*)d_out;

    const int N = in_sizes[0] / D;
    const int E = in_sizes[3];

    __half* sup = nullptr;
    cudaGetSymbolAddress((void**)&sup, g_support_h);
    __half* Wt = nullptr;
    cudaGetSymbolAddress((void**)&Wt, g_Wt_h);
    int* rp = nullptr;
    cudaGetSymbolAddress((void**)&rp, g_rowptr);

    prep_kernel<<<(D * D + 255) / 256, 256>>>(W, Wt);
    rowptr_kernel<<<(E + 255) / 256, 256>>>(edst, rp, E, N);

    const int gemm_smem = (MBLK * PADH + D * PADH) * (int)sizeof(__half); // ~52 KB
    cudaFuncSetAttribute(gemm_mma_kernel, cudaFuncAttributeMaxDynamicSharedMemorySize, gemm_smem);

    const int gemm_blocks = (N + MBLK - 1) / MBLK;
    gemm_mma_kernel<<<gemm_blocks, 256, gemm_smem>>>(x, Wt, b, sup, N);

    // one warp per node, 8 warps per block
    const int scat_blocks = (N + 7) / 8;
    scatter_csr_kernel<<<scat_blocks, 256>>>(sup, ew, esrc, rp, out, N);
}